// round 7
// baseline (speedup 1.0000x reference)
#include <cuda_runtime.h>
#include <cuda_bf16.h>
#include <math.h>

#define NPIX    768
#define NP      (NPIX * NPIX)       // 589824
#define NP4     (NP / 4)            // 147456
#define NTERMS  128
#define PPSZ    256
#define NOUT    (PPSZ * PPSZ)       // 65536
#define NBLOCKS 576                 // NP4 / 256, exact
#define NTHR    256

// Scratch for latent^T: L[I][J] = sum_n basis[n, I, J] * coeffs[n]  (2.36 MB)
__device__ float g_latent[NP];
// Monotonic grid-barrier counter. Each launch adds exactly NBLOCKS arrivals,
// and launches are serialized, so epoch = ticket/NBLOCKS is well-defined and
// no reset is ever needed (graph-replay safe, deterministic output).
__device__ unsigned long long g_bar = 0ULL;

// ---------------------------------------------------------------------------
// Single fused kernel.
// Phase 1 (all 576 blocks): HBM-streaming weighted reduction over the 128
//   basis terms — identical layout to the proven 6.45 TB/s version.
// Grid barrier: all blocks are co-resident in one wave (3.9 blocks/SM,
//   capacity 8), so an atomic arrive + spin is deadlock-free.
// Phase 2 (blocks 0..255 only): one CLIMB patch per thread from L2-resident
//   latent. Blocks 256..575 arrive and exit without spinning.
// ---------------------------------------------------------------------------
__global__ void __launch_bounds__(NTHR) fused_kernel(
    const float4* __restrict__ basis4,
    const float*  __restrict__ coeffs,
    const float*  __restrict__ wavel_ptr,
    float*        __restrict__ out)
{
    __shared__ float sc[NTERMS];
    __shared__ unsigned long long s_target;
    if (threadIdx.x < NTERMS) sc[threadIdx.x] = coeffs[threadIdx.x];
    __syncthreads();

    // ---------------- Phase 1: streaming reduction ----------------
    int idx = blockIdx.x * NTHR + threadIdx.x;   // 0 .. NP4-1 (exact)
    const float4* p = basis4 + idx;
    float4 acc = make_float4(0.f, 0.f, 0.f, 0.f);

#pragma unroll 8
    for (int n = 0; n < NTERMS; n++) {
        float4 v = p[(size_t)n * NP4];
        float  c = sc[n];
        acc.x = fmaf(v.x, c, acc.x);
        acc.y = fmaf(v.y, c, acc.y);
        acc.z = fmaf(v.z, c, acc.z);
        acc.w = fmaf(v.w, c, acc.w);
    }
    reinterpret_cast<float4*>(g_latent)[idx] = acc;

    // ---------------- Grid barrier ----------------
    __threadfence();          // make this thread's latent store globally visible
    __syncthreads();          // all threads of the block fenced
    if (threadIdx.x == 0) {
        unsigned long long ticket = atomicAdd(&g_bar, 1ULL);
        // target = end of this launch's epoch
        s_target = (ticket / NBLOCKS) * NBLOCKS + NBLOCKS;
    }
    __syncthreads();

    // Blocks that have no phase-2 work leave immediately (their arrival counts).
    if (blockIdx.x >= NOUT / NTHR) return;

    if (threadIdx.x == 0) {
        unsigned long long tgt = s_target;
        while (true) {
            unsigned long long v =
                atomicAdd(&g_bar, 0ULL);   // strong read of the counter
            if (v >= tgt) break;
            __nanosleep(64);
        }
    }
    __syncthreads();
    __threadfence();          // acquire: order counter observation before loads

    // ---------------- Phase 2: CLIMB, one patch per thread ----------------
    int o  = blockIdx.x * NTHR + threadIdx.x;    // 0 .. 65535
    int Cb = o >> 8;
    int Rb = o & 255;

    const float* base = g_latent + (3 * Cb) * NPIX + 3 * Rb;

    // Front-batch the 9 independent loads (k = 3r+c maps to base[c*768 + r])
    float z0 = base[0 * NPIX + 0];
    float z1 = base[1 * NPIX + 0];
    float z2 = base[2 * NPIX + 0];
    float z3 = base[0 * NPIX + 1];
    float z4 = base[1 * NPIX + 1];
    float z5 = base[2 * NPIX + 1];
    float z6 = base[0 * NPIX + 2];
    float z7 = base[1 * NPIX + 2];
    float z8 = base[2 * NPIX + 2];

    float zz[9] = {z0, z1, z2, z3, z4, z5, z6, z7, z8};

    // LSQ plane fit over unit 3x3 grid (orthogonal regressors):
    //   a = sum z*(x-1/2)/1.5,  b = sum z*(y-1/2)/1.5,
    //   c = mean(z) - a/2 - b/2
    float S = 0.f, Sx = 0.f, Sy = 0.f;
    bool allpos = true, allnonpos = true, anyzero = false;
#pragma unroll
    for (int k = 0; k < 9; k++) {
        float v  = zz[k];
        float xk = 0.5f * (float)(k % 3);
        float yk = 0.5f * (float)(k / 3);
        S  += v;
        Sx += v * xk;
        Sy += v * yk;
        allpos    = allpos    && (v > 0.f);
        allnonpos = allnonpos && (v <= 0.f);
        anyzero   = anyzero   || (v == 0.f);
    }
    float mean = S * (1.f / 9.f);
    float a  = (Sx - 0.5f * S) * (1.f / 1.5f);
    float b  = (Sy - 0.5f * S) * (1.f / 1.5f);
    float cc = mean - 0.5f * a - 0.5f * b;

    const float EPSF = 1e-15f;
    if (a  == 0.f) a  = EPSF;
    if (b  == 0.f) b  = EPSF;
    if (cc == 0.f) cc = EPSF;

    float x1 = (-b - cc) / a;
    float x2 = (-cc) / a;
    float lo = fminf(x1, x2);
    float hi = fmaxf(x1, x2);
    x1 = fmaxf(lo, 0.f);
    x2 = fminf(hi, 1.f);

    float ncb = (-cc) / b;
    float ab  = a / b;
    float d = x1 + ncb * x2 - 0.5f * ab * x2 * x2
                 - ncb * x1 + 0.5f * ab * x1 * x1;

    d = (d >= 0.5f)   ? d : (1.0f - d);
    d = (mean >= 0.f) ? d : (1.0f - d);
    if (allpos)    d = 1.0f;
    if (allnonpos) d = 0.0f;
    if (anyzero)   d = (d > 0.f) ? 1.0f : 0.0f;
    d = fminf(fmaxf(d, 0.f), 1.f);

    // opd = pi*d * wavel / (2*pi)
    float wl = *wavel_ptr;
    out[o] = ((float)M_PI * d) * wl * (1.0f / (2.0f * (float)M_PI));
}

extern "C" void kernel_launch(void* const* d_in, const int* in_sizes, int n_in,
                              void* d_out, int out_size)
{
    const float4* basis4 = reinterpret_cast<const float4*>(d_in[0]); // (128,768,768) f32
    const float*  coeffs = reinterpret_cast<const float*>(d_in[1]);  // (128,)
    const float*  wavel  = reinterpret_cast<const float*>(d_in[2]);  // scalar
    float*        out    = reinterpret_cast<float*>(d_out);          // (256,256) f32

    (void)in_sizes; (void)n_in; (void)out_size;

    fused_kernel<<<NBLOCKS, NTHR>>>(basis4, coeffs, wavel, out);
}